// round 17
// baseline (speedup 1.0000x reference)
#include <cuda_runtime.h>
#include <cuda_bf16.h>
#include <mma.h>
#include <cstdint>
#include <cstddef>

using namespace nvcuda;

#define BB   2
#define LL   512
#define HIN  1024
#define ENT  16
#define DD   50
#define TOT  850
#define PADN 896
#define NMASK 511
#define SCALE 0.14142135623730951f

// ---------------------------------------------------------------------------
// Scratch (device globals; zero-initialized at module load — the d=50..63
// pads of g_qh/g_ql/g_kh/g_kl rely on this and are never written).
// ---------------------------------------------------------------------------
__device__ __nv_bfloat16 g_Xh[1024 * 1024];
__device__ __nv_bfloat16 g_Xl[1024 * 1024];
__device__ __nv_bfloat16 g_WhT[2 * PADN * HIN];   // [z][n][k]
__device__ __nv_bfloat16 g_WlT[2 * PADN * HIN];
__device__ float g_conj_s[BB * LL * DD];          // e=16 slice only
__device__ float g_conj_e[BB * LL * DD];
__device__ float g_cd[BB * NMASK];
__device__ float g_fm4[4][BB][LL * LL];           // k-split partial final_mask
__device__ float g_tcos[LL * (DD / 2)];
__device__ float g_tsin[LL * (DD / 2)];
// roped q/k, bf16 hi/lo, [b][e][i][64] (d padded 50->64; pads stay zero)
__device__ __nv_bfloat16 g_qh[BB * ENT * LL * 64];
__device__ __nv_bfloat16 g_ql[BB * ENT * LL * 64];
__device__ __nv_bfloat16 g_kh[BB * ENT * LL * 64];
__device__ __nv_bfloat16 g_kl[BB * ENT * LL * 64];

// ---------------------------------------------------------------------------
// cp.async helpers (sm_80+ portable PTX)
// ---------------------------------------------------------------------------
__device__ __forceinline__ void cp_async16(void* s, const void* g)
{
    uint32_t sa = (uint32_t)__cvta_generic_to_shared(s);
    asm volatile("cp.async.ca.shared.global [%0], [%1], 16;"
                 :: "r"(sa), "l"(g) : "memory");
}
#define CP_COMMIT() asm volatile("cp.async.commit_group;" ::: "memory")
#define CP_WAIT(n)  asm volatile("cp.async.wait_group %0;" :: "n"(n) : "memory")

// ---------------------------------------------------------------------------
// Prep kernels
// ---------------------------------------------------------------------------
__global__ void split_x(const float* __restrict__ X)
{
    int idx = blockIdx.x * blockDim.x + threadIdx.x;   // 262144 float4s
    if (idx >= 1024 * 1024 / 4) return;
    float4 v = reinterpret_cast<const float4*>(X)[idx];
    __nv_bfloat16 h0 = __float2bfloat16(v.x), h1 = __float2bfloat16(v.y);
    __nv_bfloat16 h2 = __float2bfloat16(v.z), h3 = __float2bfloat16(v.w);
    __nv_bfloat16 l0 = __float2bfloat16(v.x - __bfloat162float(h0));
    __nv_bfloat16 l1 = __float2bfloat16(v.y - __bfloat162float(h1));
    __nv_bfloat16 l2 = __float2bfloat16(v.z - __bfloat162float(h2));
    __nv_bfloat16 l3 = __float2bfloat16(v.w - __bfloat162float(h3));
    __nv_bfloat162* Hp = reinterpret_cast<__nv_bfloat162*>(g_Xh);
    __nv_bfloat162* Lp = reinterpret_cast<__nv_bfloat162*>(g_Xl);
    Hp[idx * 2]     = __nv_bfloat162(h0, h1);
    Hp[idx * 2 + 1] = __nv_bfloat162(h2, h3);
    Lp[idx * 2]     = __nv_bfloat162(l0, l1);
    Lp[idx * 2 + 1] = __nv_bfloat162(l2, l3);
}

__global__ void split_wT(const float* __restrict__ W0, const float* __restrict__ W1)
{
    __shared__ __nv_bfloat16 th[32][33];
    __shared__ __nv_bfloat16 tl[32][33];
    const int z = blockIdx.z;
    const float* W = z ? W1 : W0;
    const int n0 = blockIdx.x * 32;
    const int k0 = blockIdx.y * 32;
    const int tx = threadIdx.x, ty = threadIdx.y;

    int n = n0 + tx, k = k0 + ty;
    float x = (n < TOT) ? W[(size_t)k * TOT + n] : 0.f;
    __nv_bfloat16 h = __float2bfloat16(x);
    __nv_bfloat16 l = __float2bfloat16(x - __bfloat162float(h));
    th[ty][tx] = h;
    tl[ty][tx] = l;
    __syncthreads();

    int on = n0 + ty, ok = k0 + tx;
    size_t oidx = (size_t)z * PADN * HIN + (size_t)on * HIN + ok;
    g_WhT[oidx] = th[tx][ty];
    g_WlT[oidx] = tl[tx][ty];
}

__global__ void trig_table()
{
    int idx = blockIdx.x * blockDim.x + threadIdx.x;
    if (idx >= LL * (DD / 2)) return;
    int l = idx / (DD / 2), t = idx - l * (DD / 2);
    double inv = exp(-((2.0 * t) / (double)DD) * log(10000.0));
    double ang = (double)l * inv;
    g_tcos[idx] = (float)cos(ang);
    g_tsin[idx] = (float)sin(ang);
}

// ---------------------------------------------------------------------------
// WMMA bf16 GEMM + fused RoPE + fused bf16 hi/lo split in epilogue.
// 64x64 tile, 2-stage cp.async pipeline, grid (14, 16, 2), 256 threads.
// ---------------------------------------------------------------------------
struct GemmSmemP {
    union {
        struct {
            __nv_bfloat16 Ah[2][64][40];
            __nv_bfloat16 Al[2][64][40];
            __nv_bfloat16 Bh[2][64][40];
            __nv_bfloat16 Bl[2][64][40];
        } t;
        float out[64][68];
    } u;
};
#define GEMM_SMEM sizeof(GemmSmemP)

__device__ __forceinline__ void gemm_prefetch(
    GemmSmemP* sm, int st, int kc, int m0, int n0, int tid,
    const uint4* Xh4, const uint4* Xl4, const uint4* Bh4, const uint4* Bl4)
{
    const int kc4 = kc * 4;
    #pragma unroll
    for (int it = 0; it < 4; it++) {
        int g = it * 256 + tid;
        int gg = g & 255;
        int row = gg >> 2, c8 = gg & 3;
        if (g < 256) {
            cp_async16(&sm->u.t.Ah[st][row][c8 * 8],
                       Xh4 + (size_t)(m0 + row) * 128 + kc4 + c8);
        } else if (g < 512) {
            cp_async16(&sm->u.t.Al[st][row][c8 * 8],
                       Xl4 + (size_t)(m0 + row) * 128 + kc4 + c8);
        } else if (g < 768) {
            cp_async16(&sm->u.t.Bh[st][row][c8 * 8],
                       Bh4 + (size_t)(n0 + row) * 128 + kc4 + c8);
        } else {
            cp_async16(&sm->u.t.Bl[st][row][c8 * 8],
                       Bl4 + (size_t)(n0 + row) * 128 + kc4 + c8);
        }
    }
}

__global__ __launch_bounds__(256) void gemm_wmma(
    const float* __restrict__ bias0, const float* __restrict__ bias1)
{
    extern __shared__ char dyn[];
    GemmSmemP* sm = reinterpret_cast<GemmSmemP*>(dyn);

    const int z  = blockIdx.z;
    const int n0 = blockIdx.x * 64;
    const int m0 = blockIdx.y * 64;
    const float* bias = z ? bias1 : bias0;

    const int tid = threadIdx.x;
    const int wid = tid >> 5;
    const int wr = wid & 3;
    const int wc = wid >> 2;

    const uint4* Xh4 = reinterpret_cast<const uint4*>(g_Xh);
    const uint4* Xl4 = reinterpret_cast<const uint4*>(g_Xl);
    const uint4* Bh4 = reinterpret_cast<const uint4*>(g_WhT) + (size_t)z * PADN * 128;
    const uint4* Bl4 = reinterpret_cast<const uint4*>(g_WlT) + (size_t)z * PADN * 128;

    wmma::fragment<wmma::accumulator, 16, 16, 16, float> c[2];
    wmma::fill_fragment(c[0], 0.f);
    wmma::fill_fragment(c[1], 0.f);

    gemm_prefetch(sm, 0, 0, m0, n0, tid, Xh4, Xl4, Bh4, Bl4);
    CP_COMMIT();

    for (int kc = 0; kc < 32; kc++) {
        const int cur = kc & 1;
        if (kc + 1 < 32) {
            gemm_prefetch(sm, cur ^ 1, kc + 1, m0, n0, tid, Xh4, Xl4, Bh4, Bl4);
            CP_COMMIT();
            CP_WAIT(1);
        } else {
            CP_WAIT(0);
        }
        __syncthreads();

        #pragma unroll
        for (int ks = 0; ks < 32; ks += 16) {
            wmma::fragment<wmma::matrix_a, 16, 16, 16, __nv_bfloat16, wmma::row_major> ah, al;
            wmma::fragment<wmma::matrix_b, 16, 16, 16, __nv_bfloat16, wmma::col_major> bh[2], bl[2];
            wmma::load_matrix_sync(ah, &sm->u.t.Ah[cur][wr * 16][ks], 40);
            wmma::load_matrix_sync(al, &sm->u.t.Al[cur][wr * 16][ks], 40);
            #pragma unroll
            for (int j = 0; j < 2; j++) {
                wmma::load_matrix_sync(bh[j], &sm->u.t.Bh[cur][wc * 32 + j * 16][ks], 40);
                wmma::load_matrix_sync(bl[j], &sm->u.t.Bl[cur][wc * 32 + j * 16][ks], 40);
            }
            #pragma unroll
            for (int j = 0; j < 2; j++) {
                wmma::mma_sync(c[j], ah, bh[j], c[j]);
                wmma::mma_sync(c[j], ah, bl[j], c[j]);
                wmma::mma_sync(c[j], al, bh[j], c[j]);
            }
        }
        __syncthreads();
    }

    #pragma unroll
    for (int j = 0; j < 2; j++)
        wmma::store_matrix_sync(&sm->u.out[wr * 16][wc * 32 + j * 16],
                                c[j], 68, wmma::mem_row_major);
    __syncthreads();

    __nv_bfloat16* dh = z ? g_kh : g_qh;
    __nv_bfloat16* dl = z ? g_kl : g_ql;
    float* conj_dst   = z ? g_conj_e : g_conj_s;

    for (int idx = tid; idx < 64 * 32; idx += 256) {
        int row = idx >> 5, cp = idx & 31;
        int n = n0 + cp * 2;
        if (n < TOT) {
            int e = n / DD, d = n - e * DD;
            int m = m0 + row;
            int b = m >> 9, l = m & 511;
            float v0 = sm->u.out[row][cp * 2]     + bias[n];
            float v1 = sm->u.out[row][cp * 2 + 1] + bias[n + 1];
            if (e < ENT) {
                int t = d >> 1;
                float cc = g_tcos[l * (DD / 2) + t];
                float ss = g_tsin[l * (DD / 2) + t];
                float r0 = v0 * cc - v1 * ss;
                float r1 = v1 * cc + v0 * ss;
                __nv_bfloat16 h0 = __float2bfloat16(r0);
                __nv_bfloat16 h1 = __float2bfloat16(r1);
                __nv_bfloat16 l0 = __float2bfloat16(r0 - __bfloat162float(h0));
                __nv_bfloat16 l1 = __float2bfloat16(r1 - __bfloat162float(h1));
                size_t o = (((size_t)(b * ENT + e)) * LL + l) * 64 + d;
                *reinterpret_cast<__nv_bfloat162*>(&dh[o]) =
                    __nv_bfloat162(h0, h1);
                *reinterpret_cast<__nv_bfloat162*>(&dl[o]) =
                    __nv_bfloat162(l0, l1);
            } else {
                size_t o = ((size_t)b * LL + l) * DD + d;
                conj_dst[o]     = v0;
                conj_dst[o + 1] = v1;
            }
        }
    }
}

// ---------------------------------------------------------------------------
// conj_diag — warp per (b,i), shfl reduce (fp32 e=16 slice)
// ---------------------------------------------------------------------------
__global__ __launch_bounds__(256) void conj_kernel()
{
    int wg = blockIdx.x * 8 + (threadIdx.x >> 5);
    int lane = threadIdx.x & 31;
    if (wg >= BB * NMASK) return;
    int b = wg / NMASK, i = wg - b * NMASK;
    const float* a = g_conj_s + ((size_t)b * LL + i) * DD;
    const float* c = g_conj_e + ((size_t)b * LL + i + 1) * DD;
    float s = 0.f;
    if (lane < DD)      s  = a[lane] * c[lane];
    if (lane + 32 < DD) s += a[lane + 32] * c[lane + 32];
    #pragma unroll
    for (int o = 16; o > 0; o >>= 1)
        s += __shfl_xor_sync(0xFFFFFFFFu, s, o);
    if (lane == 0) g_cd[wg] = s * SCALE;
}

// ---------------------------------------------------------------------------
// mask_kernel v5 — block = (i-pair, ks); per k-plane streams 4KB contiguous
// (rows 2i,2i+1), float4 __ldcs, 128B in flight per thread.
// grid (256, 4), 256 threads.
// ---------------------------------------------------------------------------
__global__ __launch_bounds__(256) void mask_kernel(const float* __restrict__ mask)
{
    __shared__ float scd[BB * NMASK];
    const int tid = threadIdx.x;
    for (int k = tid; k < BB * NMASK; k += 256) scd[k] = g_cd[k];

    const int i  = blockIdx.x * 2 + (tid >> 7);    // two adjacent rows
    const int ks = blockIdx.y;
    const int j  = (tid & 127) * 4;

    const int kbeg = ks * 128;
    const int kend = (ks == 3) ? NMASK : kbeg + 128;
    const float* mp = mask + (size_t)kbeg * (LL * LL) + (size_t)i * LL + j;

    __syncthreads();

    float4 a0 = make_float4(0.f, 0.f, 0.f, 0.f);
    float4 a1 = make_float4(0.f, 0.f, 0.f, 0.f);

    int k = kbeg;
    for (; k + 8 <= kend; k += 8) {
        float4 m[8];
        #pragma unroll
        for (int u = 0; u < 8; u++)
            m[u] = __ldcs(reinterpret_cast<const float4*>(
                       mp + (size_t)(k - kbeg + u) * (LL * LL)));
        #pragma unroll
        for (int u = 0; u < 8; u++) {
            float c0 = scd[k + u], c1 = scd[NMASK + k + u];
            a0.x = fmaf(c0, m[u].x, a0.x); a0.y = fmaf(c0, m[u].y, a0.y);
            a0.z = fmaf(c0, m[u].z, a0.z); a0.w = fmaf(c0, m[u].w, a0.w);
            a1.x = fmaf(c1, m[u].x, a1.x); a1.y = fmaf(c1, m[u].y, a1.y);
            a1.z = fmaf(c1, m[u].z, a1.z); a1.w = fmaf(c1, m[u].w, a1.w);
        }
    }
    for (; k < kend; k++) {
        float4 m = __ldcs(reinterpret_cast<const float4*>(
                       mp + (size_t)(k - kbeg) * (LL * LL)));
        float c0 = scd[k], c1 = scd[NMASK + k];
        a0.x = fmaf(c0, m.x, a0.x); a0.y = fmaf(c0, m.y, a0.y);
        a0.z = fmaf(c0, m.z, a0.z); a0.w = fmaf(c0, m.w, a0.w);
        a1.x = fmaf(c1, m.x, a1.x); a1.y = fmaf(c1, m.y, a1.y);
        a1.z = fmaf(c1, m.z, a1.z); a1.w = fmaf(c1, m.w, a1.w);
    }

    *reinterpret_cast<float4*>(&g_fm4[ks][0][(size_t)i * LL + j]) = a0;
    *reinterpret_cast<float4*>(&g_fm4[ks][1][(size_t)i * LL + j]) = a1;
}

// ---------------------------------------------------------------------------
// scores_wmma (R11 shape): (b, 32i x 32j) per block, split-bf16 WMMA.
// Epilogue sums the 4 k-split mask partials.
// ---------------------------------------------------------------------------
#define SS_LD   36
#define TILE_LD 72
#define SMEM_SS_BYTES   (16 * 32 * SS_LD * 4)
#define SMEM_TILE_BYTES (8 * 32 * TILE_LD * 2)
#define SCORES_SMEM     (SMEM_SS_BYTES + SMEM_TILE_BYTES)

__global__ __launch_bounds__(256) void scores_wmma(float* __restrict__ out)
{
    extern __shared__ char smem[];
    float* sS = reinterpret_cast<float*>(smem);
    __nv_bfloat16* tiles = reinterpret_cast<__nv_bfloat16*>(smem + SMEM_SS_BYTES);

    const int tid = threadIdx.x;
    const int wid = tid >> 5;
    const int j0 = blockIdx.x * 32;
    const int i0 = blockIdx.y * 32;
    const int b  = blockIdx.z;

    const uint4* qh4 = reinterpret_cast<const uint4*>(g_qh);
    const uint4* ql4 = reinterpret_cast<const uint4*>(g_ql);
    const uint4* kh4 = reinterpret_cast<const uint4*>(g_kh);
    const uint4* kl4 = reinterpret_cast<const uint4*>(g_kl);

    for (int ep = 0; ep < 8; ep++) {
        const int e0 = ep * 2;
        __syncthreads();
        #pragma unroll
        for (int it = 0; it < 8; it++) {
            int g = it * 256 + tid;
            int c   = g & 7;
            int r   = (g >> 3) & 31;
            int mat = g >> 8;
            int hl = mat & 1, el = (mat >> 1) & 1, qk = mat >> 2;
            const uint4* src = qk ? (hl ? kl4 : kh4) : (hl ? ql4 : qh4);
            int row0 = qk ? j0 : i0;
            size_t gi = ((size_t)(b * ENT + e0 + el) * LL + row0 + r) * 8 + c;
            uint4 v = src[gi];
            *reinterpret_cast<uint4*>(
                &tiles[((qk * 4 + el * 2 + hl) * 32 + r) * TILE_LD + c * 8]) = v;
        }
        __syncthreads();

        const int el  = wid >> 2;
        const int qi  = ((wid >> 1) & 1) * 16;
        const int qj  = (wid & 1) * 16;
        const __nv_bfloat16* Qh_ = &tiles[((el * 2 + 0) * 32 + qi) * TILE_LD];
        const __nv_bfloat16* Ql_ = &tiles[((el * 2 + 1) * 32 + qi) * TILE_LD];
        const __nv_bfloat16* Kh_ = &tiles[((4 + el * 2 + 0) * 32 + qj) * TILE_LD];
        const __nv_bfloat16* Kl_ = &tiles[((4 + el * 2 + 1) * 32 + qj) * TILE_LD];

        wmma::fragment<wmma::accumulator, 16, 16, 16, float> acc;
        wmma::fill_fragment(acc, 0.f);
        #pragma unroll
        for (int ks = 0; ks < 64; ks += 16) {
            wmma::fragment<wmma::matrix_a, 16, 16, 16, __nv_bfloat16, wmma::row_major> ah, al;
            wmma::fragment<wmma::matrix_b, 16, 16, 16, __nv_bfloat16, wmma::col_major> bh, bl;
            wmma::load_matrix_sync(ah, Qh_ + ks, TILE_LD);
            wmma::load_matrix_sync(al, Ql_ + ks, TILE_LD);
            wmma::load_matrix_sync(bh, Kh_ + ks, TILE_LD);
            wmma::load_matrix_sync(bl, Kl_ + ks, TILE_LD);
            wmma::mma_sync(acc, ah, bh, acc);
            wmma::mma_sync(acc, ah, bl, acc);
            wmma::mma_sync(acc, al, bh, acc);
        }
        wmma::store_matrix_sync(&sS[(e0 + el) * 32 * SS_LD + qi * SS_LD + qj],
                                acc, SS_LD, wmma::mem_row_major);
    }
    __syncthreads();

    for (int v = 0; v < 4; v++) {
        int lin = v * 256 + tid;
        int jj = lin & 31, ii = lin >> 5;
        int i = i0 + ii, j = j0 + jj;
        size_t fidx = (size_t)i * LL + j;
        float fm = (g_fm4[0][b][fidx] + g_fm4[1][b][fidx]) +
                   (g_fm4[2][b][fidx] + g_fm4[3][b][fidx]);
        float* op = out + ((((size_t)b * LL + i) * LL + j) * ENT);
        const float* sp = &sS[ii * SS_LD + jj];
        #pragma unroll
        for (int q = 0; q < 4; q++) {
            float4 w;
            w.x = fmaf(sp[(4 * q + 0) * 32 * SS_LD], SCALE, fm);
            w.y = fmaf(sp[(4 * q + 1) * 32 * SS_LD], SCALE, fm);
            w.z = fmaf(sp[(4 * q + 2) * 32 * SS_LD], SCALE, fm);
            w.w = fmaf(sp[(4 * q + 3) * 32 * SS_LD], SCALE, fm);
            *reinterpret_cast<float4*>(op + 4 * q) = w;
        }
    }
}

// ---------------------------------------------------------------------------
extern "C" void kernel_launch(void* const* d_in, const int* in_sizes, int n_in,
                              void* d_out, int out_size)
{
    const float* X    = (const float*)d_in[0];
    const float* mask = (const float*)d_in[1];
    const float* Ws   = (const float*)d_in[2];
    const float* bs   = (const float*)d_in[3];
    const float* We   = (const float*)d_in[4];
    const float* be   = (const float*)d_in[5];
    float* out        = (float*)d_out;

    cudaFuncSetAttribute(scores_wmma,
        cudaFuncAttributeMaxDynamicSharedMemorySize, SCORES_SMEM);
    cudaFuncSetAttribute(gemm_wmma,
        cudaFuncAttributeMaxDynamicSharedMemorySize, GEMM_SMEM);

    split_x<<<(1024 * 1024 / 4 + 255) / 256, 256>>>(X);
    split_wT<<<dim3(PADN / 32, HIN / 32, 2), dim3(32, 32)>>>(Ws, We);
    trig_table<<<(LL * (DD / 2) + 255) / 256, 256>>>();

    gemm_wmma<<<dim3(PADN / 64, 1024 / 64, 2), 256, GEMM_SMEM>>>(bs, be);

    conj_kernel<<<(BB * NMASK + 7) / 8, 256>>>();

    mask_kernel<<<dim3(LL / 2, 4), 256>>>(mask);
    scores_wmma<<<dim3(LL / 32, LL / 32, 2), 256, SCORES_SMEM>>>(out);
}